// round 2
// baseline (speedup 1.0000x reference)
#include <cuda_runtime.h>

#define B_TOK   8192
#define INDIM   1024
#define OUTDIM  1024
#define NE      8
// TOP_K = 2 (hardcoded in router logic)

// ---------------- device scratch (static; no allocations allowed) ----------
__device__ int   g_count[NE];
__device__ int   g_offset[NE];
__device__ int   g_tok [NE * B_TOK];
__device__ float g_gate[NE * B_TOK];
// H scratch: total assignments = 2*B_TOK rows of OUTDIM floats (64 MB)
__device__ float g_H[(size_t)2 * B_TOK * OUTDIM];

// ---------------- helpers ---------------------------------------------------
__global__ void zero_counts_kernel() {
    if (threadIdx.x < NE) g_count[threadIdx.x] = 0;
}

__global__ void offsets_kernel() {
    if (threadIdx.x == 0) {
        int s = 0;
        #pragma unroll
        for (int e = 0; e < NE; e++) { g_offset[e] = s; s += g_count[e]; }
    }
}

// ---------------- router: logits, top-2, softmax gating, bucket append ------
__global__ void router_kernel(const float* __restrict__ x,
                              const float* __restrict__ rw,
                              const float* __restrict__ rb,
                              float* __restrict__ gating_out /* may be null */) {
    const int warp = threadIdx.x >> 5;
    const int lane = threadIdx.x & 31;
    const int t = blockIdx.x * 8 + warp;
    if (t >= B_TOK) return;

    const float* xr = x + (size_t)t * INDIM;
    float acc[NE];
    #pragma unroll
    for (int e = 0; e < NE; e++) acc[e] = 0.f;

    for (int i = lane; i < INDIM; i += 32) {
        float xv = xr[i];
        const float4* r4 = reinterpret_cast<const float4*>(rw + (size_t)i * NE);
        float4 a = r4[0], b = r4[1];
        acc[0] += xv * a.x; acc[1] += xv * a.y; acc[2] += xv * a.z; acc[3] += xv * a.w;
        acc[4] += xv * b.x; acc[5] += xv * b.y; acc[6] += xv * b.z; acc[7] += xv * b.w;
    }
    #pragma unroll
    for (int e = 0; e < NE; e++) {
        #pragma unroll
        for (int off = 16; off; off >>= 1)
            acc[e] += __shfl_down_sync(0xffffffffu, acc[e], off);
    }

    if (lane == 0) {
        float lg[NE];
        #pragma unroll
        for (int e = 0; e < NE; e++) lg[e] = acc[e] + rb[e];

        // top-1 (strict > keeps smallest index on ties, matching jax top_k)
        int e1 = 0;
        #pragma unroll
        for (int e = 1; e < NE; e++) if (lg[e] > lg[e1]) e1 = e;
        // top-2
        int e2 = -1;
        #pragma unroll
        for (int e = 0; e < NE; e++) {
            if (e == e1) continue;
            if (e2 < 0 || lg[e] > lg[e2]) e2 = e;
        }

        float v1 = lg[e1], v2 = lg[e2];
        float ex = expf(v2 - v1);         // v2 <= v1, safe
        float denom = 1.f + ex;
        float g1 = 1.f / denom;
        float g2 = ex / denom;

        if (gating_out) {
            float grow[NE];
            #pragma unroll
            for (int e = 0; e < NE; e++) grow[e] = 0.f;
            grow[e1] = g1; grow[e2] = g2;
            float* gp = gating_out + (size_t)t * NE;
            #pragma unroll
            for (int e = 0; e < NE; e++) gp[e] = grow[e];
        }

        int p1 = atomicAdd(&g_count[e1], 1);
        g_tok [e1 * B_TOK + p1] = t;
        g_gate[e1 * B_TOK + p1] = g1;
        int p2 = atomicAdd(&g_count[e2], 1);
        g_tok [e2 * B_TOK + p2] = t;
        g_gate[e2 * B_TOK + p2] = g2;
    }
}

// ---------------- grouped GEMM stage 1: H = relu(Xg @ W1[e] + b1[e]) --------
// 128x128 tile, 8x8 per thread, K-step 8, 256 threads.
__global__ __launch_bounds__(256, 2)
void gemm1_kernel(const float* __restrict__ x,
                  const float* __restrict__ w1,
                  const float* __restrict__ b1) {
    const int e = blockIdx.z;
    const int cnt = g_count[e];
    const int m0 = blockIdx.y * 128;
    if (m0 >= cnt) return;
    const int n0 = blockIdx.x * 128;

    __shared__ float As[8][132];   // [kk][row]
    __shared__ float Bs[8][132];   // [kk][col]

    const int tid = threadIdx.x;
    // A-load: thread -> (row, k-quad)
    const int arow = tid >> 1;          // 0..127
    const int akk  = (tid & 1) * 4;     // 0 or 4
    const int grow = m0 + arow;
    const float* xrow = nullptr;
    if (grow < cnt) xrow = x + (size_t)g_tok[e * B_TOK + grow] * INDIM;
    // B-load: thread -> (kk, col-quad)
    const int bkk  = tid >> 5;          // 0..7
    const int bcol = (tid & 31) * 4;    // 0..124
    const float* wbase = w1 + ((size_t)e << 20) + n0 + bcol;

    const int tx = tid & 15, ty = tid >> 4;
    float acc[8][8];
    #pragma unroll
    for (int i = 0; i < 8; i++)
        #pragma unroll
        for (int j = 0; j < 8; j++) acc[i][j] = 0.f;

    for (int k0 = 0; k0 < INDIM; k0 += 8) {
        float4 av = make_float4(0.f, 0.f, 0.f, 0.f);
        if (xrow) av = *reinterpret_cast<const float4*>(xrow + k0 + akk);
        float4 bv = *reinterpret_cast<const float4*>(wbase + (size_t)(k0 + bkk) * OUTDIM);

        __syncthreads();
        As[akk + 0][arow] = av.x;
        As[akk + 1][arow] = av.y;
        As[akk + 2][arow] = av.z;
        As[akk + 3][arow] = av.w;
        *reinterpret_cast<float4*>(&Bs[bkk][bcol]) = bv;
        __syncthreads();

        #pragma unroll
        for (int kk = 0; kk < 8; kk++) {
            float a[8], b[8];
            *reinterpret_cast<float4*>(&a[0]) = *reinterpret_cast<const float4*>(&As[kk][ty * 8]);
            *reinterpret_cast<float4*>(&a[4]) = *reinterpret_cast<const float4*>(&As[kk][ty * 8 + 4]);
            *reinterpret_cast<float4*>(&b[0]) = *reinterpret_cast<const float4*>(&Bs[kk][tx * 8]);
            *reinterpret_cast<float4*>(&b[4]) = *reinterpret_cast<const float4*>(&Bs[kk][tx * 8 + 4]);
            #pragma unroll
            for (int i = 0; i < 8; i++)
                #pragma unroll
                for (int j = 0; j < 8; j++)
                    acc[i][j] += a[i] * b[j];
        }
    }

    // epilogue: relu(acc + b1), store to H scratch
    const int hbase = g_offset[e];
    const float* bp = b1 + (size_t)e * OUTDIM + n0 + tx * 8;
    float4 b1a = *reinterpret_cast<const float4*>(bp);
    float4 b1b = *reinterpret_cast<const float4*>(bp + 4);

    #pragma unroll
    for (int i = 0; i < 8; i++) {
        int m = m0 + ty * 8 + i;
        if (m >= cnt) break;
        float* hrow = g_H + (size_t)(hbase + m) * OUTDIM + n0 + tx * 8;
        float4 v0, v1;
        v0.x = fmaxf(acc[i][0] + b1a.x, 0.f);
        v0.y = fmaxf(acc[i][1] + b1a.y, 0.f);
        v0.z = fmaxf(acc[i][2] + b1a.z, 0.f);
        v0.w = fmaxf(acc[i][3] + b1a.w, 0.f);
        v1.x = fmaxf(acc[i][4] + b1b.x, 0.f);
        v1.y = fmaxf(acc[i][5] + b1b.y, 0.f);
        v1.z = fmaxf(acc[i][6] + b1b.z, 0.f);
        v1.w = fmaxf(acc[i][7] + b1b.w, 0.f);
        *reinterpret_cast<float4*>(hrow)     = v0;
        *reinterpret_cast<float4*>(hrow + 4) = v1;
    }
}

// ---------------- grouped GEMM stage 2: fused += gate * (H @ W2[e] + b2[e]) -
__global__ __launch_bounds__(256, 2)
void gemm2_kernel(const float* __restrict__ w2,
                  const float* __restrict__ b2,
                  float* __restrict__ fused) {
    const int e = blockIdx.z;
    const int cnt = g_count[e];
    const int m0 = blockIdx.y * 128;
    if (m0 >= cnt) return;
    const int n0 = blockIdx.x * 128;
    const int hbase = g_offset[e];

    __shared__ float As[8][132];
    __shared__ float Bs[8][132];

    const int tid = threadIdx.x;
    const int arow = tid >> 1;
    const int akk  = (tid & 1) * 4;
    const int grow = m0 + arow;
    const float* hrow_ld = nullptr;
    if (grow < cnt) hrow_ld = g_H + (size_t)(hbase + grow) * OUTDIM;
    const int bkk  = tid >> 5;
    const int bcol = (tid & 31) * 4;
    const float* wbase = w2 + ((size_t)e << 20) + n0 + bcol;

    const int tx = tid & 15, ty = tid >> 4;
    float acc[8][8];
    #pragma unroll
    for (int i = 0; i < 8; i++)
        #pragma unroll
        for (int j = 0; j < 8; j++) acc[i][j] = 0.f;

    for (int k0 = 0; k0 < OUTDIM; k0 += 8) {
        float4 av = make_float4(0.f, 0.f, 0.f, 0.f);
        if (hrow_ld) av = *reinterpret_cast<const float4*>(hrow_ld + k0 + akk);
        float4 bv = *reinterpret_cast<const float4*>(wbase + (size_t)(k0 + bkk) * OUTDIM);

        __syncthreads();
        As[akk + 0][arow] = av.x;
        As[akk + 1][arow] = av.y;
        As[akk + 2][arow] = av.z;
        As[akk + 3][arow] = av.w;
        *reinterpret_cast<float4*>(&Bs[bkk][bcol]) = bv;
        __syncthreads();

        #pragma unroll
        for (int kk = 0; kk < 8; kk++) {
            float a[8], b[8];
            *reinterpret_cast<float4*>(&a[0]) = *reinterpret_cast<const float4*>(&As[kk][ty * 8]);
            *reinterpret_cast<float4*>(&a[4]) = *reinterpret_cast<const float4*>(&As[kk][ty * 8 + 4]);
            *reinterpret_cast<float4*>(&b[0]) = *reinterpret_cast<const float4*>(&Bs[kk][tx * 8]);
            *reinterpret_cast<float4*>(&b[4]) = *reinterpret_cast<const float4*>(&Bs[kk][tx * 8 + 4]);
            #pragma unroll
            for (int i = 0; i < 8; i++)
                #pragma unroll
                for (int j = 0; j < 8; j++)
                    acc[i][j] += a[i] * b[j];
        }
    }

    const float* bp = b2 + (size_t)e * OUTDIM + n0 + tx * 8;
    float bb[8];
    *reinterpret_cast<float4*>(&bb[0]) = *reinterpret_cast<const float4*>(bp);
    *reinterpret_cast<float4*>(&bb[4]) = *reinterpret_cast<const float4*>(bp + 4);

    #pragma unroll
    for (int i = 0; i < 8; i++) {
        int m = m0 + ty * 8 + i;
        if (m >= cnt) break;
        int tok = g_tok[e * B_TOK + m];
        float gate = g_gate[e * B_TOK + m];
        float* frow = fused + (size_t)tok * OUTDIM + n0 + tx * 8;
        #pragma unroll
        for (int j = 0; j < 8; j++)
            atomicAdd(&frow[j], gate * (acc[i][j] + bb[j]));
    }
}

// ---------------- launch -----------------------------------------------------
extern "C" void kernel_launch(void* const* d_in, const int* in_sizes, int n_in,
                              void* d_out, int out_size) {
    const float* x  = (const float*)d_in[0];
    const float* rw = (const float*)d_in[1];
    const float* rb = (const float*)d_in[2];
    const float* w1 = (const float*)d_in[3];
    const float* b1 = (const float*)d_in[4];
    const float* w2 = (const float*)d_in[5];
    const float* b2 = (const float*)d_in[6];

    float* fused = (float*)d_out;
    const size_t fused_elems = (size_t)B_TOK * OUTDIM;
    float* gating_out = nullptr;
    if ((size_t)out_size >= fused_elems + (size_t)B_TOK * NE)
        gating_out = fused + fused_elems;

    // zero fused accumulator region (poisoned by harness)
    cudaMemsetAsync(d_out, 0, fused_elems * sizeof(float), 0);

    zero_counts_kernel<<<1, 32>>>();
    router_kernel<<<B_TOK / 8, 256>>>(x, rw, rb, gating_out);
    offsets_kernel<<<1, 32>>>();

    dim3 grid(OUTDIM / 128, B_TOK / 128, NE);   // (8, 64, 8)
    gemm1_kernel<<<grid, 256>>>(x, w1, b1);
    gemm2_kernel<<<grid, 256>>>(w2, b2, fused);
}

// round 4
// speedup vs baseline: 2.2317x; 2.2317x over previous
#include <cuda_runtime.h>
#include <cuda_bf16.h>
#include <cstdint>

#define B_TOK   8192
#define NE      8
#define DIM     1024
#define TM      128
#define TN      128
#define KC      32
#define NCHUNK  (DIM / KC)
#define ASTRIDE 80                     // 64B data + 16B pad per smem row
#define A_BYTES (128 * ASTRIDE)        // 10240 per operand-split tile
#define BUF_BYTES (4 * A_BYTES)        // Ahi | Alo | Bhi | Blo
#define SMEM_DYN (2 * BUF_BYTES)       // 81920

// ---------------- static device scratch ------------------------------------
__device__ int   g_count[NE];
__device__ int   g_off[NE];
__device__ int   g_tok [NE * B_TOK];
__device__ float g_gate[NE * B_TOK];
#define PAD_ROWS (2 * B_TOK + NE * 128)
__device__ __nv_bfloat16 g_Hhi[(size_t)PAD_ROWS * DIM];
__device__ __nv_bfloat16 g_Hlo[(size_t)PAD_ROWS * DIM];
__device__ __nv_bfloat16 g_wthi[(size_t)2 * NE * DIM * DIM];  // [mtx][e][n][k]
__device__ __nv_bfloat16 g_wtlo[(size_t)2 * NE * DIM * DIM];

// ---------------- helpers ----------------------------------------------------
__device__ __forceinline__ uint32_t smem_u32(const void* p) {
    uint32_t a;
    asm("{ .reg .u64 t; cvta.to.shared.u64 t, %1; cvt.u32.u64 %0, t; }" : "=r"(a) : "l"(p));
    return a;
}

#define LDSM4(r, a) \
    asm volatile("ldmatrix.sync.aligned.m8n8.x4.shared.b16 {%0,%1,%2,%3}, [%4];" \
        : "=r"((r)[0]), "=r"((r)[1]), "=r"((r)[2]), "=r"((r)[3]) : "r"(a))

#define MMA16816(c, a, b0v, b1v) \
    asm volatile("mma.sync.aligned.m16n8k16.row.col.f32.bf16.bf16.f32 " \
        "{%0,%1,%2,%3},{%4,%5,%6,%7},{%8,%9},{%0,%1,%2,%3};" \
        : "+f"((c)[0]), "+f"((c)[1]), "+f"((c)[2]), "+f"((c)[3]) \
        : "r"((a)[0]), "r"((a)[1]), "r"((a)[2]), "r"((a)[3]), "r"(b0v), "r"(b1v))

// ---------------- small kernels ---------------------------------------------
__global__ void zero_counts_kernel() { if (threadIdx.x < NE) g_count[threadIdx.x] = 0; }

__global__ void offsets_kernel() {
    if (threadIdx.x == 0) {
        int s = 0;
        #pragma unroll
        for (int e = 0; e < NE; e++) { g_off[e] = s; s += (g_count[e] + 127) & ~127; }
    }
}

__global__ void router_kernel(const float* __restrict__ x,
                              const float* __restrict__ rw,
                              const float* __restrict__ rb,
                              float* __restrict__ gating_out) {
    const int warp = threadIdx.x >> 5, lane = threadIdx.x & 31;
    const int t = blockIdx.x * 8 + warp;
    if (t >= B_TOK) return;
    const float* xr = x + (size_t)t * DIM;
    float acc[NE];
    #pragma unroll
    for (int e = 0; e < NE; e++) acc[e] = 0.f;
    for (int i = lane; i < DIM; i += 32) {
        float xv = xr[i];
        const float4* r4 = reinterpret_cast<const float4*>(rw + (size_t)i * NE);
        float4 a = r4[0], b = r4[1];
        acc[0] += xv * a.x; acc[1] += xv * a.y; acc[2] += xv * a.z; acc[3] += xv * a.w;
        acc[4] += xv * b.x; acc[5] += xv * b.y; acc[6] += xv * b.z; acc[7] += xv * b.w;
    }
    #pragma unroll
    for (int e = 0; e < NE; e++)
        #pragma unroll
        for (int off = 16; off; off >>= 1) acc[e] += __shfl_down_sync(0xffffffffu, acc[e], off);
    if (lane == 0) {
        float lg[NE];
        #pragma unroll
        for (int e = 0; e < NE; e++) lg[e] = acc[e] + rb[e];
        int e1 = 0;
        #pragma unroll
        for (int e = 1; e < NE; e++) if (lg[e] > lg[e1]) e1 = e;
        int e2 = -1;
        #pragma unroll
        for (int e = 0; e < NE; e++) { if (e == e1) continue; if (e2 < 0 || lg[e] > lg[e2]) e2 = e; }
        float ex = expf(lg[e2] - lg[e1]);
        float g1 = 1.f / (1.f + ex), g2 = ex / (1.f + ex);
        if (gating_out) {
            float grow[NE];
            #pragma unroll
            for (int e = 0; e < NE; e++) grow[e] = 0.f;
            grow[e1] = g1; grow[e2] = g2;
            float* gp = gating_out + (size_t)t * NE;
            #pragma unroll
            for (int e = 0; e < NE; e++) gp[e] = grow[e];
        }
        int p1 = atomicAdd(&g_count[e1], 1);
        g_tok[e1 * B_TOK + p1] = t; g_gate[e1 * B_TOK + p1] = g1;
        int p2 = atomicAdd(&g_count[e2], 1);
        g_tok[e2 * B_TOK + p2] = t; g_gate[e2 * B_TOK + p2] = g2;
    }
}

// transpose + bf16-split weights: w[mtx][e][k][n] -> wt{hi,lo}[mtx][e][n][k]
__global__ __launch_bounds__(256, 4)
void wsplit_kernel(const float* __restrict__ w1, const float* __restrict__ w2) {
    __shared__ float t[32][33];
    const int z = blockIdx.z;                 // mtx*8 + e
    const float* w = ((z >> 3) ? w2 : w1) + ((size_t)(z & 7) << 20);
    __nv_bfloat16* dh = g_wthi + ((size_t)z << 20);
    __nv_bfloat16* dl = g_wtlo + ((size_t)z << 20);
    const int n0 = blockIdx.x * 32, k0 = blockIdx.y * 32;
    const int tx = threadIdx.x & 31, ty = threadIdx.x >> 5;
    #pragma unroll
    for (int i = 0; i < 4; i++)
        t[ty + 8 * i][tx] = w[(size_t)(k0 + ty + 8 * i) * DIM + n0 + tx];
    __syncthreads();
    #pragma unroll
    for (int i = 0; i < 4; i++) {
        float v = t[tx][ty + 8 * i];
        __nv_bfloat16 h = __float2bfloat16(v);
        __nv_bfloat16 l = __float2bfloat16(v - __bfloat162float(h));
        size_t o = (size_t)(n0 + ty + 8 * i) * DIM + k0 + tx;
        dh[o] = h; dl[o] = l;
    }
}

// ---------------- grouped GEMM: bf16x3 mma.sync ------------------------------
template <int STAGE>
__global__ __launch_bounds__(256, 1)
void gemm_mma(const float* __restrict__ x, const float* __restrict__ bias,
              float* __restrict__ fused) {
    const int e   = blockIdx.z;
    const int cnt = g_count[e];
    const int m0  = blockIdx.y * TM;
    if (m0 >= cnt) return;
    const int n0     = blockIdx.x * TN;
    const int padoff = g_off[e];

    extern __shared__ char smem[];
    const uint32_t sbase = smem_u32(smem);
    const int tid  = threadIdx.x;
    const int lane = tid & 31, warp = tid >> 5;
    const int wm = (warp >> 2) * 64, wn = (warp & 3) * 32;

    // global-load mapping: row = tid>>1 (0..127), half = tid&1 (16 elems)
    const int arow = tid >> 1, ahalf = tid & 1;
    const float* aptr = nullptr;
    const __nv_bfloat16 *ahip = nullptr, *alop = nullptr;
    if (m0 + arow < cnt) {
        if (STAGE == 1) aptr = x + (size_t)g_tok[e * B_TOK + m0 + arow] * DIM;
        else {
            size_t r = (size_t)(padoff + m0 + arow) * DIM;
            ahip = g_Hhi + r; alop = g_Hlo + r;
        }
    }
    const size_t wb = ((size_t)((STAGE - 1) * NE + e) << 20) + (size_t)(n0 + arow) * DIM;
    const __nv_bfloat16* bhp = g_wthi + wb;
    const __nv_bfloat16* blp = g_wtlo + wb;

    float acc[4][4][4];
    #pragma unroll
    for (int i = 0; i < 4; i++)
        #pragma unroll
        for (int j = 0; j < 4; j++)
            #pragma unroll
            for (int k = 0; k < 4; k++) acc[i][j][k] = 0.f;

    float4 la[4];
    uint4  lah[2], lal[2], lbh[2], lbl[2];
    const uint4 z4 = make_uint4(0u, 0u, 0u, 0u);

    auto loadRegs = [&](int c) {
        const int kb = c * KC + ahalf * 16;
        lbh[0] = *reinterpret_cast<const uint4*>(bhp + kb);
        lbh[1] = *reinterpret_cast<const uint4*>(bhp + kb + 8);
        lbl[0] = *reinterpret_cast<const uint4*>(blp + kb);
        lbl[1] = *reinterpret_cast<const uint4*>(blp + kb + 8);
        if (STAGE == 1) {
            if (aptr) {
                #pragma unroll
                for (int i = 0; i < 4; i++)
                    la[i] = *reinterpret_cast<const float4*>(aptr + kb + 4 * i);
            } else {
                #pragma unroll
                for (int i = 0; i < 4; i++) la[i] = make_float4(0.f, 0.f, 0.f, 0.f);
            }
        } else {
            if (ahip) {
                lah[0] = *reinterpret_cast<const uint4*>(ahip + kb);
                lah[1] = *reinterpret_cast<const uint4*>(ahip + kb + 8);
                lal[0] = *reinterpret_cast<const uint4*>(alop + kb);
                lal[1] = *reinterpret_cast<const uint4*>(alop + kb + 8);
            } else { lah[0] = z4; lah[1] = z4; lal[0] = z4; lal[1] = z4; }
        }
    };

    auto storeSmem = [&](int buf) {
        char* bb = smem + buf * BUF_BYTES;
        const uint32_t ao = arow * ASTRIDE + ahalf * 32;
        if (STAGE == 1) {
            __nv_bfloat16 hh[16], ll[16];
            const float* f = reinterpret_cast<const float*>(la);
            #pragma unroll
            for (int i = 0; i < 16; i++) {
                float v = f[i];
                __nv_bfloat16 h = __float2bfloat16(v);
                hh[i] = h;
                ll[i] = __float2bfloat16(v - __bfloat162float(h));
            }
            *reinterpret_cast<uint4*>(bb + ao)      = *reinterpret_cast<uint4*>(hh);
            *reinterpret_cast<uint4*>(bb + ao + 16) = *reinterpret_cast<uint4*>(hh + 8);
            *reinterpret_cast<uint4*>(bb + A_BYTES + ao)      = *reinterpret_cast<uint4*>(ll);
            *reinterpret_cast<uint4*>(bb + A_BYTES + ao + 16) = *reinterpret_cast<uint4*>(ll + 8);
        } else {
            *reinterpret_cast<uint4*>(bb + ao)      = lah[0];
            *reinterpret_cast<uint4*>(bb + ao + 16) = lah[1];
            *reinterpret_cast<uint4*>(bb + A_BYTES + ao)      = lal[0];
            *reinterpret_cast<uint4*>(bb + A_BYTES + ao + 16) = lal[1];
        }
        *reinterpret_cast<uint4*>(bb + 2 * A_BYTES + ao)      = lbh[0];
        *reinterpret_cast<uint4*>(bb + 2 * A_BYTES + ao + 16) = lbh[1];
        *reinterpret_cast<uint4*>(bb + 3 * A_BYTES + ao)      = lbl[0];
        *reinterpret_cast<uint4*>(bb + 3 * A_BYTES + ao + 16) = lbl[1];
    };

    auto compute = [&](int buf) {
        const uint32_t sb = sbase + buf * BUF_BYTES;
        const uint32_t lrow = lane & 15, lcol = (lane >> 4) * 16;
        #pragma unroll
        for (int ks = 0; ks < 2; ks++) {
            const uint32_t ko = ks * 32;
            uint32_t ah[4][4], al[4][4];
            #pragma unroll
            for (int mt = 0; mt < 4; mt++) {
                uint32_t aa = sb + (wm + mt * 16 + lrow) * ASTRIDE + lcol + ko;
                LDSM4(ah[mt], aa);
                LDSM4(al[mt], aa + A_BYTES);
            }
            uint32_t bh4[2][4], bl4[2][4];
            #pragma unroll
            for (int p = 0; p < 2; p++) {
                uint32_t ba = sb + 2 * A_BYTES + (wn + p * 16 + lrow) * ASTRIDE + lcol + ko;
                LDSM4(bh4[p], ba);
                LDSM4(bl4[p], ba + A_BYTES);
            }
            #pragma unroll
            for (int mt = 0; mt < 4; mt++)
                #pragma unroll
                for (int nt = 0; nt < 4; nt++) {
                    const int p = nt >> 1, o = nt & 1;
                    MMA16816(acc[mt][nt], ah[mt], bh4[p][o], bh4[p][o + 2]);
                    MMA16816(acc[mt][nt], ah[mt], bl4[p][o], bl4[p][o + 2]);
                    MMA16816(acc[mt][nt], al[mt], bh4[p][o], bh4[p][o + 2]);
                }
        }
    };

    loadRegs(0);
    storeSmem(0);
    __syncthreads();
    for (int c = 0; c < NCHUNK; c++) {
        if (c + 1 < NCHUNK) loadRegs(c + 1);
        compute(c & 1);
        if (c + 1 < NCHUNK) storeSmem((c + 1) & 1);
        __syncthreads();
    }

    // ---- epilogue ----
    const float* bp = bias + (size_t)e * DIM + n0 + wn;
    float2 bs[4];
    #pragma unroll
    for (int nt = 0; nt < 4; nt++)
        bs[nt] = *reinterpret_cast<const float2*>(bp + nt * 8 + (lane & 3) * 2);

    #pragma unroll
    for (int mt = 0; mt < 4; mt++) {
        #pragma unroll
        for (int h = 0; h < 2; h++) {
            const int m = m0 + wm + mt * 16 + (lane >> 2) + h * 8;
            if (m >= cnt) continue;
            if (STAGE == 1) {
                size_t rb = (size_t)(padoff + m) * DIM + n0 + wn + (lane & 3) * 2;
                #pragma unroll
                for (int nt = 0; nt < 4; nt++) {
                    float vx = fmaxf(acc[mt][nt][2 * h]     + bs[nt].x, 0.f);
                    float vy = fmaxf(acc[mt][nt][2 * h + 1] + bs[nt].y, 0.f);
                    __nv_bfloat162 hi2, lo2;
                    hi2.x = __float2bfloat16(vx);
                    hi2.y = __float2bfloat16(vy);
                    lo2.x = __float2bfloat16(vx - __bfloat162float(hi2.x));
                    lo2.y = __float2bfloat16(vy - __bfloat162float(hi2.y));
                    *reinterpret_cast<__nv_bfloat162*>(&g_Hhi[rb + nt * 8]) = hi2;
                    *reinterpret_cast<__nv_bfloat162*>(&g_Hlo[rb + nt * 8]) = lo2;
                }
            } else {
                const int tok = g_tok[e * B_TOK + m];
                const float g = g_gate[e * B_TOK + m];
                float* fr = fused + (size_t)tok * DIM + n0 + wn + (lane & 3) * 2;
                #pragma unroll
                for (int nt = 0; nt < 4; nt++) {
                    atomicAdd(&fr[nt * 8],     g * (acc[mt][nt][2 * h]     + bs[nt].x));
                    atomicAdd(&fr[nt * 8 + 1], g * (acc[mt][nt][2 * h + 1] + bs[nt].y));
                }
            }
        }
    }
}

// ---------------- launch ------------------------------------------------------
extern "C" void kernel_launch(void* const* d_in, const int* in_sizes, int n_in,
                              void* d_out, int out_size) {
    const float* x  = (const float*)d_in[0];
    const float* rw = (const float*)d_in[1];
    const float* rb = (const float*)d_in[2];
    const float* w1 = (const float*)d_in[3];
    const float* b1 = (const float*)d_in[4];
    const float* w2 = (const float*)d_in[5];
    const float* b2 = (const float*)d_in[6];

    float* fused = (float*)d_out;
    const size_t fused_elems = (size_t)B_TOK * DIM;
    float* gating_out = nullptr;
    if ((size_t)out_size >= fused_elems + (size_t)B_TOK * NE)
        gating_out = fused + fused_elems;

    cudaFuncSetAttribute(gemm_mma<1>, cudaFuncAttributeMaxDynamicSharedMemorySize, SMEM_DYN);
    cudaFuncSetAttribute(gemm_mma<2>, cudaFuncAttributeMaxDynamicSharedMemorySize, SMEM_DYN);

    cudaMemsetAsync(d_out, 0, fused_elems * sizeof(float), 0);

    zero_counts_kernel<<<1, 32>>>();
    wsplit_kernel<<<dim3(32, 32, 16), 256>>>(w1, w2);
    router_kernel<<<B_TOK / 8, 256>>>(x, rw, rb, gating_out);
    offsets_kernel<<<1, 32>>>();

    dim3 grid(DIM / TN, 64, NE);   // (8, 64, 8); blocks past cnt exit early
    gemm_mma<1><<<grid, 256, SMEM_DYN>>>(x, b1, fused);
    gemm_mma<2><<<grid, 256, SMEM_DYN>>>(nullptr, b2, fused);
}